// round 3
// baseline (speedup 1.0000x reference)
#include <cuda_runtime.h>
#include <cstddef>

// Problem constants (fixed by the dataset)
#define E_DIM 128
#define S_DIM 64
#define P_DIM 256
#define B_DIM 4096

// ---------------------------------------------------------------------------
// Persistent device scratch for the path metadata, sorted by output segment.
// (No cudaMalloc allowed; __device__ globals are the sanctioned scratch.)
// ---------------------------------------------------------------------------
__device__ int   d_seg_start[S_DIM + 1];   // segment s3 spans [seg_start[s3], seg_start[s3+1])
__device__ int   d_path_i1[P_DIM];         // i1 * E  (pre-scaled row offset into x)
__device__ int   d_path_i2[P_DIM];         // i2 * E
__device__ float d_path_c [P_DIM];         // path coefficient

// ---------------------------------------------------------------------------
// Prep kernel: deterministic stable counting-sort of the 256 paths by i3.
// One block, 256 threads; runs every launch (graph-replay safe, ~2 us).
// ---------------------------------------------------------------------------
__global__ void prep_paths_kernel(const float* __restrict__ path_coeff,
                                  const int*   __restrict__ path_idx)
{
    __shared__ int s_i3[P_DIM];
    __shared__ int s_cnt[S_DIM + 1];

    const int t = threadIdx.x;               // 0..255
    const int i1 = path_idx[t * 3 + 0];
    const int i2 = path_idx[t * 3 + 1];
    const int i3 = path_idx[t * 3 + 2];
    s_i3[t] = i3;
    if (t <= S_DIM) s_cnt[t] = 0;
    __syncthreads();

    atomicAdd(&s_cnt[i3 + 1], 1);
    __syncthreads();

    if (t == 0) {                            // inclusive prefix over 65 ints
        int acc = 0;
        #pragma unroll
        for (int i = 0; i <= S_DIM; i++) { acc += s_cnt[i]; s_cnt[i] = acc; }
    }
    __syncthreads();

    if (t <= S_DIM) d_seg_start[t] = s_cnt[t];

    // Stable rank within my segment: count earlier paths with the same i3.
    int rank = 0;
    for (int j = 0; j < t; j++) rank += (s_i3[j] == i3) ? 1 : 0;
    const int pos = s_cnt[i3] + rank;

    d_path_i1[pos] = i1 * E_DIM;
    d_path_i2[pos] = i2 * E_DIM;
    d_path_c [pos] = path_coeff[t];
}

// ---------------------------------------------------------------------------
// Main kernel: one CTA per batch row b. 128 threads, thread t owns e-lane t.
// x-row and y-row staged in shared (32 KB each, float4 coalesced loads).
// Paths are grouped by output segment, so the accumulator is a register.
// ---------------------------------------------------------------------------
#define ROW_FLOATS (S_DIM * E_DIM)          // 8192 floats = 32 KB
#define SMEM_FLOATS (2 * ROW_FLOATS + (S_DIM + 1) + 3 * P_DIM)
#define SMEM_BYTES  (SMEM_FLOATS * 4)

__global__ __launch_bounds__(128, 3)
void seg_poly_kernel(const float* __restrict__ x_table,
                     const float* __restrict__ y,
                     const int*   __restrict__ x_idx,
                     float*       __restrict__ out)
{
    extern __shared__ float smem[];
    float* sx   = smem;                       // [ROW_FLOATS]
    float* sy   = smem + ROW_FLOATS;          // [ROW_FLOATS]
    int*   sseg = (int*)  (smem + 2 * ROW_FLOATS);            // [S+1]
    int*   si1  = sseg + (S_DIM + 1);                         // [P]
    int*   si2  = si1 + P_DIM;                                // [P]
    float* sc   = (float*)(si2 + P_DIM);                      // [P]

    const int b = blockIdx.x;
    const int t = threadIdx.x;                // 0..127

    // Stage x-row (gathered) and y-row into shared with float4 loads.
    const size_t xrow = (size_t)x_idx[b] * ROW_FLOATS;
    const float4* xr = (const float4*)(x_table + xrow);
    const float4* yr = (const float4*)(y + (size_t)b * ROW_FLOATS);
    float4* sx4 = (float4*)sx;
    float4* sy4 = (float4*)sy;
    #pragma unroll
    for (int i = 0; i < (ROW_FLOATS / 4) / 128; i++) {        // 16 iters
        sx4[t + i * 128] = xr[t + i * 128];
        sy4[t + i * 128] = yr[t + i * 128];
    }

    // Stage path metadata.
    if (t <= S_DIM) sseg[t] = d_seg_start[t];
    #pragma unroll
    for (int i = t; i < P_DIM; i += 128) {
        si1[i] = d_path_i1[i];
        si2[i] = d_path_i2[i];
        sc [i] = d_path_c [i];
    }
    __syncthreads();

    // Walk output segments in order; accumulator lives in a register.
    float* orow = out + (size_t)b * ROW_FLOATS + t;
    #pragma unroll 4
    for (int s3 = 0; s3 < S_DIM; s3++) {
        const int beg = sseg[s3];
        const int end = sseg[s3 + 1];
        float acc = 0.0f;
        for (int j = beg; j < end; j++) {
            acc = fmaf(sc[j] * sx[si1[j] + t], sy[si2[j] + t], acc);
        }
        orow[(size_t)s3 * E_DIM] = acc;       // empty segments write 0
    }
}

// ---------------------------------------------------------------------------
// Launch wrapper. Inputs (metadata order):
//   0: x_table  f32 [N, S*E]
//   1: y        f32 [B, S*E]
//   2: path_coeff f32 [P]
//   3: x_idx    i32 [B]
//   4: path_idx i32 [P, 3]
// Output: f32 [B, S*E]
// ---------------------------------------------------------------------------
extern "C" void kernel_launch(void* const* d_in, const int* in_sizes, int n_in,
                              void* d_out, int out_size)
{
    const float* x_table    = (const float*)d_in[0];
    const float* y          = (const float*)d_in[1];
    const float* path_coeff = (const float*)d_in[2];
    const int*   x_idx      = (const int*)  d_in[3];
    const int*   path_idx   = (const int*)  d_in[4];
    float*       out        = (float*)d_out;

    (void)in_sizes; (void)n_in; (void)out_size;

    static bool attr_set = false;
    if (!attr_set) {
        cudaFuncSetAttribute(seg_poly_kernel,
                             cudaFuncAttributeMaxDynamicSharedMemorySize,
                             SMEM_BYTES);
        attr_set = true;
    }

    prep_paths_kernel<<<1, P_DIM>>>(path_coeff, path_idx);
    seg_poly_kernel<<<B_DIM, 128, SMEM_BYTES>>>(x_table, y, x_idx, out);
}